// round 15
// baseline (speedup 1.0000x reference)
#include <cuda_runtime.h>
#include <cstdint>

#define B_DIM 2048
#define K_DIM 256
#define U_DIM 512

#define BM 64
#define BN 64
#define BK 16
#define NTILES (K_DIM / BK)   // 16
#define SY_STRIDE (BM + 4)    // 68 floats = 272B row (16B-aligned)

typedef unsigned long long u64t;

// ---- packed f32x2 helpers (sm_103a) ----
__device__ __forceinline__ u64t f2_fma(u64t a, u64t b, u64t c) {
    u64t d;
    asm("fma.rn.f32x2 %0, %1, %2, %3;" : "=l"(d) : "l"(a), "l"(b), "l"(c));
    return d;
}
__device__ __forceinline__ u64t f2_mul(u64t a, u64t b) {
    u64t d;
    asm("mul.rn.f32x2 %0, %1, %2;" : "=l"(d) : "l"(a), "l"(b));
    return d;
}
__device__ __forceinline__ u64t f2_pack(float a, float b) {
    u64t d;
    asm("mov.b64 %0, {%1, %2};" : "=l"(d) : "f"(a), "f"(b));
    return d;
}
__device__ __forceinline__ float2 f2_unpack(u64t v) {
    float2 r;
    asm("mov.b64 {%0, %1}, %2;" : "=f"(r.x), "=f"(r.y) : "l"(v));
    return r;
}

__global__ __launch_bounds__(256, 2)
void pew_kernel(const float* __restrict__ x,
                const float* __restrict__ w,
                float* __restrict__ out) {
    // sY: y = 1 - x transposed to [k][b] (b contiguous); sW: -w in [k][u].
    __shared__ __align__(16) float sY[2][BK][SY_STRIDE];
    __shared__ __align__(16) float sW[2][BK][BN];

    const int tid = threadIdx.x;
    const int tx  = tid & 15;          // u: 16 threads x 4 cols
    const int ty  = tid >> 4;          // b: 16 threads x 4 rows
    const int ub  = blockIdx.x * BN;
    const int bb  = blockIdx.y * BM;

    // staging coordinates
    const int xb0 = tid >> 2;          // 0..63 : x row within tile
    const int xkq = (tid & 3) * 4;     // k-quad within tile
    const int wu  = (tid & 15) * 4;    // u offset for w float4
    const int wk  = tid >> 4;          // k row for w float4

    const u64t ONE2 = 0x3F8000003F800000ULL; // {1.0f, 1.0f}

    u64t acc[2][4];                    // [b-pair][u], packed over b
#pragma unroll
    for (int i = 0; i < 2; i++)
#pragma unroll
        for (int j = 0; j < 4; j++) acc[i][j] = ONE2;

    // ---- stage tile 0 ----
    float4 rx = *(const float4*)(x + (bb + xb0) * K_DIM + xkq);
    float4 rw = *(const float4*)(w + wk * U_DIM + ub + wu);

    sY[0][xkq + 0][xb0] = 1.0f - rx.x;
    sY[0][xkq + 1][xb0] = 1.0f - rx.y;
    sY[0][xkq + 2][xb0] = 1.0f - rx.z;
    sY[0][xkq + 3][xb0] = 1.0f - rx.w;
    {
        float4 nw = make_float4(-rw.x, -rw.y, -rw.z, -rw.w);
        *(float4*)&sW[0][wk][wu] = nw;
    }
    __syncthreads();

#pragma unroll 1
    for (int t = 0; t < NTILES; t++) {
        const int cur = t & 1;

        // prefetch next tile from global (overlaps with compute below)
        if (t + 1 < NTILES) {
            const int k0 = (t + 1) * BK;
            rx = *(const float4*)(x + (bb + xb0) * K_DIM + k0 + xkq);
            rw = *(const float4*)(w + (k0 + wk) * U_DIM + ub + wu);
        }

        // ---- compute on buffer `cur`, SW-pipelined one k-step ahead ----
        ulonglong2 ya = *(const ulonglong2*)&sY[cur][0][ty * 4];
        float4     wv = *(const float4*)&sW[cur][0][tx * 4];

#pragma unroll
        for (int k = 0; k < BK; k++) {
            // issue k+1's loads BEFORE consuming k's operands, so the LDS
            // latency is covered by this warp's own 24 packed ops.
            ulonglong2 ya_n;
            float4     wv_n;
            if (k + 1 < BK) {
                ya_n = *(const ulonglong2*)&sY[cur][k + 1][ty * 4];
                wv_n = *(const float4*)&sW[cur][k + 1][tx * 4];
            }

            u64t wp[4];
            wp[0] = f2_pack(wv.x, wv.x);
            wp[1] = f2_pack(wv.y, wv.y);
            wp[2] = f2_pack(wv.z, wv.z);
            wp[3] = f2_pack(wv.w, wv.w);

            const u64t yv[2] = {ya.x, ya.y};
#pragma unroll
            for (int i = 0; i < 2; i++)
#pragma unroll
                for (int j = 0; j < 4; j++) {
                    // term = 1 + (-w)*(1-x);  acc *= term  via
                    //   p = (-w)*(1-x);  acc = p*acc + acc
                    const u64t p = f2_mul(wp[j], yv[i]);
                    acc[i][j] = f2_fma(p, acc[i][j], acc[i][j]);
                }

            if (k + 1 < BK) { ya = ya_n; wv = wv_n; }
        }

        // ---- store prefetched tile into the other buffer ----
        if (t + 1 < NTILES) {
            const int nb = cur ^ 1;
            sY[nb][xkq + 0][xb0] = 1.0f - rx.x;
            sY[nb][xkq + 1][xb0] = 1.0f - rx.y;
            sY[nb][xkq + 2][xb0] = 1.0f - rx.z;
            sY[nb][xkq + 3][xb0] = 1.0f - rx.w;
            float4 nw = make_float4(-rw.x, -rw.y, -rw.z, -rw.w);
            *(float4*)&sW[nb][wk][wu] = nw;
            __syncthreads();
        }
    }

    // ---- epilogue: unpack b-pairs, vectorized STG.128 ----
    const int ob = bb + ty * 4;
    const int ou = ub + tx * 4;
#pragma unroll
    for (int i = 0; i < 2; i++) {
        const float2 c0 = f2_unpack(acc[i][0]);
        const float2 c1 = f2_unpack(acc[i][1]);
        const float2 c2 = f2_unpack(acc[i][2]);
        const float2 c3 = f2_unpack(acc[i][3]);
        float4 vlo = make_float4(c0.x, c1.x, c2.x, c3.x);
        float4 vhi = make_float4(c0.y, c1.y, c2.y, c3.y);
        *(float4*)(out + (ob + i * 2 + 0) * U_DIM + ou) = vlo;
        *(float4*)(out + (ob + i * 2 + 1) * U_DIM + ou) = vhi;
    }
}

extern "C" void kernel_launch(void* const* d_in, const int* in_sizes, int n_in,
                              void* d_out, int out_size) {
    const float* x = (const float*)d_in[0];   // [2048, 256]
    const float* w = (const float*)d_in[1];   // [256 * 512], k-major, u contiguous
    float* out = (float*)d_out;               // [2048, 512]

    dim3 grid(U_DIM / BN, B_DIM / BM);        // (8, 32) = 256 blocks
    pew_kernel<<<grid, 256>>>(x, w, out);
}